// round 1
// baseline (speedup 1.0000x reference)
#include <cuda_runtime.h>

// scattering_59210419142945 — GB300 sm_103a
//
// Algebraic collapse: Lmat in the reference is exactly diagonal
// (diag(deg) * outer(dhalf,dhalf)), so eigh yields a signed permutation and
// every filter matrix g_j = V diag(lam_j) V^T is diagonal with entries
// lam_j(E_v), E_v = deg_v / max(1, deg_v). The scattering cascade reduces to
// per-node scalar weights a_j[v] = lam_j(E_v) applied to |f|.
//
// out[0:128]                     = mean_v f[v,d]
// out[128 + j*128 + d]           = mean_v a_j[v] * |f[v,d]|
// out[1152 + (u*8+j)*128 + d]    = mean_v a_u[v] * a_j[v] * |f[v,d]|

#define V_NODES 2048
#define D_F     128
#define J_F     8
#define NROWS   73            // 1 + 8 + 64
#define NBLK3   128
#define CHUNK3  (V_NODES / NBLK3)   // 16

// scratch (no allocations allowed)
__device__ float g_deg[V_NODES];
__device__ float g_a[V_NODES * J_F];                 // AoS: [v][j]
__device__ float g_partial[NBLK3 * NROWS * D_F];     // 4.8 MB, lives in L2

// ---------------------------------------------------------------------------
// k1: deg[row] = sum_col W[row][col].  One warp per row, float4 loads,
// pairwise-in-lane + shuffle-tree reduce (keeps fp32 error ~1e-6).
// ---------------------------------------------------------------------------
__global__ void __launch_bounds__(256) k1_rowsum(const float* __restrict__ W) {
    int warp = threadIdx.x >> 5;
    int lane = threadIdx.x & 31;
    int row  = blockIdx.x * 8 + warp;
    const float4* Wr = reinterpret_cast<const float4*>(W + (size_t)row * V_NODES);
    float s = 0.0f;
#pragma unroll
    for (int i = 0; i < V_NODES / (32 * 4); ++i) {   // 16 iterations
        float4 v = Wr[lane + 32 * i];
        s += (v.x + v.y) + (v.z + v.w);
    }
#pragma unroll
    for (int o = 16; o > 0; o >>= 1)
        s += __shfl_xor_sync(0xffffffffu, s, o);
    if (lane == 0) g_deg[row] = s;
}

// ---------------------------------------------------------------------------
// k2: filter responses per node.  Mirrors the reference fp32 expression order.
//   A = 3*ln(2)/6 = ln(2)/2
//   wav_i(E) = ghat(ln E - A*i/3), i = 1..7   (rows 1..7, j = 2..8)
//   ghat(x)  = (x > -A && x <= 0) ? 0.5 + 0.5*cos(2*pi*(x/A + 0.5)) : 0
//   scal(E)  = sqrt(max(1.125 - sum_i wav_i^2, 0))        (row 0)
// ---------------------------------------------------------------------------
__global__ void k2_filters() {
    int v = blockIdx.x * blockDim.x + threadIdx.x;
    if (v >= V_NODES) return;
    const float A      = 0.34657359027997264f;
    const float TWO_PI = 6.283185307179586f;

    float deg = g_deg[v];
    float E   = fabsf(deg / fmaxf(1.0f, deg));
    float lnE = logf(E);

    float wav[7];
    float ssum = 0.0f;
#pragma unroll
    for (int i = 1; i <= 7; ++i) {
        float x = lnE - A * (float)i / 3.0f;
        float w = 0.0f;
        if (x > -A && x <= 0.0f) {
            float t = x / A + 0.5f;
            w = 0.5f + 0.5f * cosf(TWO_PI * t);
        }
        wav[i - 1] = w;
        ssum += w * w;
    }
    float scal = sqrtf(fmaxf(1.125f - ssum, 0.0f));

    g_a[v * J_F + 0] = fabsf(scal);
#pragma unroll
    for (int i = 0; i < 7; ++i)
        g_a[v * J_F + 1 + i] = fabsf(wav[i]);
}

// ---------------------------------------------------------------------------
// k3: per-block (v-chunk) partial sums of all 73 output rows.
// thread d handles feature dim d; 73 register accumulators; f read once.
// ---------------------------------------------------------------------------
__global__ void __launch_bounds__(128) k3_acc(const float* __restrict__ f) {
    int d  = threadIdx.x;
    int v0 = blockIdx.x * CHUNK3;

    float acc0 = 0.0f;
    float acc1[8];
    float acc2[64];
#pragma unroll
    for (int j = 0; j < 8; ++j) acc1[j] = 0.0f;
#pragma unroll
    for (int i = 0; i < 64; ++i) acc2[i] = 0.0f;

    for (int vi = 0; vi < CHUNK3; ++vi) {
        int v = v0 + vi;
        float fv = __ldg(f + (size_t)v * D_F + d);
        float af = fabsf(fv);
        float4 a_lo = *reinterpret_cast<const float4*>(g_a + v * J_F);
        float4 a_hi = *reinterpret_cast<const float4*>(g_a + v * J_F + 4);
        float a[8] = {a_lo.x, a_lo.y, a_lo.z, a_lo.w,
                      a_hi.x, a_hi.y, a_hi.z, a_hi.w};

        acc0 += fv;
#pragma unroll
        for (int j = 0; j < 8; ++j)
            acc1[j] = fmaf(a[j], af, acc1[j]);
#pragma unroll
        for (int u = 0; u < 8; ++u) {
            float pu = a[u] * af;
#pragma unroll
            for (int j = 0; j < 8; ++j)
                acc2[u * 8 + j] = fmaf(pu, a[j], acc2[u * 8 + j]);
        }
    }

    float* p = g_partial + (size_t)blockIdx.x * (NROWS * D_F);
    p[0 * D_F + d] = acc0;
#pragma unroll
    for (int j = 0; j < 8; ++j) p[(1 + j) * D_F + d] = acc1[j];
#pragma unroll
    for (int i = 0; i < 64; ++i) p[(9 + i) * D_F + d] = acc2[i];
}

// ---------------------------------------------------------------------------
// k4: deterministic cross-block reduction + mean (writes every out element
// exactly once, so no memset of the poisoned d_out is needed).
// ---------------------------------------------------------------------------
__global__ void __launch_bounds__(128) k4_reduce(float* __restrict__ out) {
    int r = blockIdx.x;
    int d = threadIdx.x;
    float s = 0.0f;
#pragma unroll 8
    for (int b = 0; b < NBLK3; ++b)
        s += g_partial[(size_t)b * (NROWS * D_F) + r * D_F + d];
    out[r * D_F + d] = s * (1.0f / 2048.0f);
}

// ---------------------------------------------------------------------------
extern "C" void kernel_launch(void* const* d_in, const int* in_sizes, int n_in,
                              void* d_out, int out_size) {
    const float* W = (const float*)d_in[0];
    const float* f = (const float*)d_in[1];
    // defensive: if metadata ordering ever flips, detect by size
    if (n_in >= 2 && in_sizes[0] == V_NODES * D_F && in_sizes[1] == V_NODES * V_NODES) {
        const float* t = W; W = f; f = t;
    }
    float* out = (float*)d_out;

    k1_rowsum<<<V_NODES / 8, 256>>>(W);
    k2_filters<<<(V_NODES + 255) / 256, 256>>>();
    k3_acc<<<NBLK3, 128>>>(f);
    k4_reduce<<<NROWS, 128>>>(out);
}

// round 2
// speedup vs baseline: 1.2025x; 1.2025x over previous
#include <cuda_runtime.h>

// scattering_59210419142945 — GB300 sm_103a  (R2)
//
// Algebraic collapse (see R1): Lmat is exactly diagonal, so the scattering
// cascade reduces to per-node scalar weights a_j[v] applied to |f|:
//   out[0:128]                  = mean_v f[v,d]
//   out[128 + j*128 + d]        = mean_v a_j[v] * |f[v,d]|
//   out[1152 + (u*8+j)*128 + d] = mean_v a_u[v]*a_j[v]*|f[v,d]|
//
// R2 changes: k2 fused into k1; k3 uses 256 threads (v-split + smem combine);
// k4 uses 1024 threads/block (8-way parallel partial sum + smem tree) to fix
// the 14us latency-bound reduction seen in ncu.

#define V_NODES 2048
#define D_F     128
#define J_F     8
#define NROWS   73                    // 1 + 8 + 64
#define NBLK3   128
#define CHUNK3  (V_NODES / NBLK3)     // 16

__device__ float g_a[V_NODES * J_F];                 // AoS: [v][j]
__device__ float g_partial[NBLK3 * NROWS * D_F];     // 4.8 MB

// ---------------------------------------------------------------------------
// k1: row-sum of W (one warp per row, float4, shuffle tree) + fused filter
// evaluation in lane 0.  A = ln(2)/2; raised-cosine wavelets j=2..8 and the
// scaling residual, matching the reference fp32 expression order.
// ---------------------------------------------------------------------------
__global__ void __launch_bounds__(256) k1_rowsum_filters(const float* __restrict__ W) {
    int warp = threadIdx.x >> 5;
    int lane = threadIdx.x & 31;
    int row  = blockIdx.x * 8 + warp;
    const float4* Wr = reinterpret_cast<const float4*>(W + (size_t)row * V_NODES);
    float s = 0.0f;
#pragma unroll
    for (int i = 0; i < V_NODES / (32 * 4); ++i) {   // 16 iterations
        float4 v = Wr[lane + 32 * i];
        s += (v.x + v.y) + (v.z + v.w);
    }
#pragma unroll
    for (int o = 16; o > 0; o >>= 1)
        s += __shfl_xor_sync(0xffffffffu, s, o);

    if (lane == 0) {
        const float A      = 0.34657359027997264f;   // ln(2)/2
        const float TWO_PI = 6.283185307179586f;
        float deg = s;
        float E   = fabsf(deg / fmaxf(1.0f, deg));
        float lnE = logf(E);

        float wav[7];
        float ssum = 0.0f;
#pragma unroll
        for (int i = 1; i <= 7; ++i) {
            float x = lnE - A * (float)i / 3.0f;
            float w = 0.0f;
            if (x > -A && x <= 0.0f) {
                float t = x / A + 0.5f;
                w = 0.5f + 0.5f * cosf(TWO_PI * t);
            }
            wav[i - 1] = w;
            ssum += w * w;
        }
        float scal = sqrtf(fmaxf(1.125f - ssum, 0.0f));

        g_a[row * J_F + 0] = fabsf(scal);
#pragma unroll
        for (int i = 0; i < 7; ++i)
            g_a[row * J_F + 1 + i] = fabsf(wav[i]);
    }
}

// ---------------------------------------------------------------------------
// k3: per-block partial sums of all 73 rows.  256 threads: group g = tid>>7
// handles 8 of the block's 16 nodes; groups combine through shared memory.
// ---------------------------------------------------------------------------
__global__ void __launch_bounds__(256) k3_acc(const float* __restrict__ f) {
    __shared__ float sm[NROWS * D_F];                // 37.4 KB
    int d  = threadIdx.x & 127;
    int g  = threadIdx.x >> 7;                       // 0 or 1
    int v0 = blockIdx.x * CHUNK3 + g * (CHUNK3 / 2);

    float acc0 = 0.0f;
    float acc1[8];
    float acc2[64];
#pragma unroll
    for (int j = 0; j < 8; ++j) acc1[j] = 0.0f;
#pragma unroll
    for (int i = 0; i < 64; ++i) acc2[i] = 0.0f;

#pragma unroll
    for (int vi = 0; vi < CHUNK3 / 2; ++vi) {
        int v = v0 + vi;
        float fv = __ldg(f + (size_t)v * D_F + d);
        float af = fabsf(fv);
        float4 a_lo = *reinterpret_cast<const float4*>(g_a + v * J_F);
        float4 a_hi = *reinterpret_cast<const float4*>(g_a + v * J_F + 4);
        float a[8] = {a_lo.x, a_lo.y, a_lo.z, a_lo.w,
                      a_hi.x, a_hi.y, a_hi.z, a_hi.w};

        acc0 += fv;
#pragma unroll
        for (int j = 0; j < 8; ++j)
            acc1[j] = fmaf(a[j], af, acc1[j]);
#pragma unroll
        for (int u = 0; u < 8; ++u) {
            float pu = a[u] * af;
#pragma unroll
            for (int j = 0; j < 8; ++j)
                acc2[u * 8 + j] = fmaf(pu, a[j], acc2[u * 8 + j]);
        }
    }

    if (g == 0) {
        sm[0 * D_F + d] = acc0;
#pragma unroll
        for (int j = 0; j < 8; ++j) sm[(1 + j) * D_F + d] = acc1[j];
#pragma unroll
        for (int i = 0; i < 64; ++i) sm[(9 + i) * D_F + d] = acc2[i];
    }
    __syncthreads();
    if (g == 1) {
        float* p = g_partial + (size_t)blockIdx.x * (NROWS * D_F);
        p[0 * D_F + d] = sm[0 * D_F + d] + acc0;
#pragma unroll
        for (int j = 0; j < 8; ++j)
            p[(1 + j) * D_F + d] = sm[(1 + j) * D_F + d] + acc1[j];
#pragma unroll
        for (int i = 0; i < 64; ++i)
            p[(9 + i) * D_F + d] = sm[(9 + i) * D_F + d] + acc2[i];
    }
}

// ---------------------------------------------------------------------------
// k4: cross-block reduction.  Block r, 1024 threads: 8 sub-reducers per
// output element (each sums 16 partials, fully unrolled -> 16 in-flight
// loads/thread), then a fixed-order smem combine.  Deterministic.
// ---------------------------------------------------------------------------
__global__ void __launch_bounds__(1024) k4_reduce(float* __restrict__ out) {
    __shared__ float sm[8 * D_F];
    int r = blockIdx.x;
    int d = threadIdx.x & 127;
    int c = threadIdx.x >> 7;                        // 0..7
    const float* base = g_partial + (size_t)r * D_F + d;

    float s = 0.0f;
#pragma unroll
    for (int i = 0; i < 16; ++i) {
        int b = c * 16 + i;
        s += base[(size_t)b * (NROWS * D_F)];
    }
    sm[c * D_F + d] = s;
    __syncthreads();
    if (c == 0) {
        float t = sm[d];
#pragma unroll
        for (int cc = 1; cc < 8; ++cc)
            t += sm[cc * D_F + d];
        out[r * D_F + d] = t * (1.0f / 2048.0f);
    }
}

// ---------------------------------------------------------------------------
extern "C" void kernel_launch(void* const* d_in, const int* in_sizes, int n_in,
                              void* d_out, int out_size) {
    const float* W = (const float*)d_in[0];
    const float* f = (const float*)d_in[1];
    if (n_in >= 2 && in_sizes[0] == V_NODES * D_F && in_sizes[1] == V_NODES * V_NODES) {
        const float* t = W; W = f; f = t;
    }
    float* out = (float*)d_out;

    k1_rowsum_filters<<<V_NODES / 8, 256>>>(W);
    k3_acc<<<NBLK3, 256>>>(f);
    k4_reduce<<<NROWS, 1024>>>(out);
}